// round 14
// baseline (speedup 1.0000x reference)
#include <cuda_runtime.h>
#include <cstdint>

#define NW 16
#define NEUR 128
#define NPTS 65536
#define TILE 128
#define THREADS 256
#define INV_SIGMA 50.0f
#define HALO 3
#define NSLOT (2*HALO+1)
#define HSP 132              // hs row pitch (floats); 16B-aligned rows
#define CHUNK 32
#define NCHNK 8
#define NCTA 296             // 2 per SM x 148 SMs, persistent

typedef unsigned long long ull;

__device__ int   g_cnt[NW];          // statically zero; reduce re-zeros each run
__device__ int   g_work;
__device__ int   g_list[NW * NPTS];
__device__ float g_part[NSLOT * NPTS];

static __device__ __forceinline__ float tanh_approx(float x) {
    float r; asm("tanh.approx.f32 %0, %1;" : "=f"(r) : "f"(x)); return r;
}
static __device__ __forceinline__ float sigmoid_fast(float x) {
    return 1.0f / (1.0f + __expf(-x));
}
static __device__ __forceinline__ void ffma2(ull& d, ull a, ull b) {
    asm("fma.rn.f32x2 %0, %1, %2, %0;" : "+l"(d) : "l"(a), "l"(b));
}
static __device__ __forceinline__ ull pack2(float lo, float hi) {
    ull r; asm("mov.b64 %0, {%1, %2};" : "=l"(r) : "f"(lo), "f"(hi)); return r;
}
static __device__ __forceinline__ float2 unpack2(ull v) {
    float2 r; asm("mov.b64 {%0, %1}, %2;" : "=f"(r.x), "=f"(r.y) : "l"(v)); return r;
}
static __device__ __forceinline__ uint32_t smem_u32(const void* p) {
    uint32_t a;
    asm("{ .reg .u64 t; cvta.to.shared.u64 t, %1; cvt.u32.u64 %0, t; }" : "=r"(a) : "l"(p));
    return a;
}
static __device__ __forceinline__ void cp16(uint32_t dst, const void* src) {
    asm volatile("cp.async.ca.shared.global [%0], [%1], 16;" :: "r"(dst), "l"(src));
}
#define CP_COMMIT() asm volatile("cp.async.commit_group;" ::: "memory")
#define CP_WAIT(n)  asm volatile("cp.async.wait_group %0;" :: "n"(n) : "memory")

// ---------------- small kernels ----------------
// Two-level counter aggregation: smem ranks per CTA, ONE global atomic per
// (CTA, window) -> 256 atomics/address instead of ~900 serialized leaders.
__global__ void build_lists(const float* __restrict__ x) {
    __shared__ int scount[NW];
    __shared__ int sbase[NW];
    const int tid = threadIdx.x;
    const int p   = blockIdx.x * blockDim.x + tid;

    if (tid < NW) scount[tid] = 0;
    __syncthreads();

    float xv = x[p];
    int h = min(NW - 1, max(0, (int)floorf(xv * (float)NW)));

    int rank[NSLOT];
    #pragma unroll
    for (int dw = -HALO; dw <= HALO; dw++) {
        int w = h + dw;
        rank[dw + HALO] = (w >= 0 && w < NW) ? atomicAdd(&scount[w], 1) : -1;
    }
    __syncthreads();

    if (tid < NW) sbase[tid] = (scount[tid] > 0)
                             ? atomicAdd(&g_cnt[tid], scount[tid]) : 0;
    __syncthreads();

    #pragma unroll
    for (int dw = -HALO; dw <= HALO; dw++) {
        int w = h + dw;
        if (rank[dw + HALO] >= 0)
            g_list[w * NPTS + sbase[w] + rank[dw + HALO]] = p;
    }
}

__global__ void fbpinn_reduce(const float* __restrict__ x, float* __restrict__ out) {
    int n = blockIdx.x * blockDim.x + threadIdx.x;
    if (n < NPTS) {
        int h = min(NW - 1, max(0, (int)floorf(x[n] * (float)NW)));
        float s = 0.0f;
        #pragma unroll
        for (int dw = -HALO; dw <= HALO; dw++) {
            int w = h + dw;
            if (w >= 0 && w < NW) s += g_part[(dw + HALO) * NPTS + n];
        }
        out[n] = s;
        // reset counters for the next graph replay
        if (n < NW) g_cnt[n] = 0;
        if (n == NW) g_work = 0;
    }
}

// ---------------- main kernel: persistent, 2 CTAs/SM (unchanged) ----------------
__global__ __launch_bounds__(THREADS, 2) void fbpinn_kernel(
    const float* __restrict__ x,    const float* __restrict__ means,
    const float* __restrict__ stdv, const float* __restrict__ mids,
    const float* __restrict__ W_in, const float* __restrict__ b_in,
    const float* __restrict__ W_hid,const float* __restrict__ b_hid,
    const float* __restrict__ W_out,const float* __restrict__ b_out)
{
    extern __shared__ float smem[];
    float* hs    = smem;                       // [128][132]  67584 B
    float* Wb    = hs + NEUR * HSP;            // [2][32][128] 32768 B ping-pong
    float* xsn   = Wb + 2 * CHUNK * NEUR;      // [128]
    float* xsr   = xsn + TILE;
    int*   sidx  = (int*)(xsr + TILE);
    float* win   = (float*)(sidx + TILE);
    float* bin   = win + NEUR;
    float* wo    = bin + NEUR;
    float* bs0   = wo + NEUR;
    float* bs1   = bs0 + NEUR;
    float* opart = bs1 + NEUR;                 // [8][128]
    int*   pref  = (int*)(opart + 8 * TILE);   // [NW+1]
    int*   itm   = pref + NW + 1;              // [1]

    const int tid = threadIdx.x;
    const int p4  = tid & 31;                  // point quad: 4*p4 .. 4*p4+3
    const int fbi = tid >> 5;                  // feature block 0..7
    const int fb  = fbi * 16;

    if (tid == 0) {
        int s = 0;
        pref[0] = 0;
        #pragma unroll
        for (int i = 0; i < NW; i++) {
            s += (g_cnt[i] + TILE - 1) / TILE;
            pref[i + 1] = s;
        }
    }
    __syncthreads();
    const int total = pref[NW];
    const size_t lstep = (size_t)NW * NEUR * NEUR;

    for (;;) {
        if (tid == 0) itm[0] = atomicAdd(&g_work, 1);
        __syncthreads();
        const int item = itm[0];
        if (item >= total) break;

        int w = 0;
        #pragma unroll
        for (int i = 1; i < NW; i++) if (item >= pref[i]) w = i;
        const int p0  = (item - pref[w]) * TILE;
        const int cnt = g_cnt[w];
        const size_t wbase = (size_t)w * NEUR * NEUR;

        #define ISSUE_CHUNK(g) do {                                              \
            const char* _src = (const char*)(W_hid + ((g) >> 2) * lstep + wbase  \
                                             + ((g) & 3) * CHUNK * NEUR);        \
            uint32_t _dst = smem_u32(Wb + ((g) & 1) * CHUNK * NEUR);             \
            _Pragma("unroll")                                                    \
            for (int _i = 0; _i < 4; _i++)                                       \
                cp16(_dst + (tid + _i * THREADS) * 16,                           \
                     _src + (tid + _i * THREADS) * 16);                          \
        } while (0)

        ISSUE_CHUNK(0);
        CP_COMMIT();

        if (tid < TILE) {
            int i = p0 + tid;
            int idx = g_list[w * NPTS + ((i < cnt) ? i : p0)];
            sidx[tid] = (i < cnt) ? idx : -1;
            float xv = x[idx];
            xsr[tid] = xv;
            xsn[tid] = (xv - means[w]) / stdv[w];
        }
        if (tid < NEUR) {
            win[tid] = W_in[w * NEUR + tid];
            bin[tid] = b_in[w * NEUR + tid];
            wo[tid]  = W_out[w * NEUR + tid];
            bs0[tid] = b_hid[(size_t)w * NEUR + tid];
            bs1[tid] = b_hid[(size_t)(NW + w) * NEUR + tid];
        }
        __syncthreads();

        // ---- layer 0: 4 points x 16 features per thread ----
        {
            float4 xn = *(const float4*)&xsn[4 * p4];
            #pragma unroll
            for (int f = 0; f < 16; f++) {
                int fg = fb + f;
                float wf = win[fg], bf = bin[fg];
                float4 hv;
                hv.x = tanh_approx(fmaf(xn.x, wf, bf));
                hv.y = tanh_approx(fmaf(xn.y, wf, bf));
                hv.z = tanh_approx(fmaf(xn.z, wf, bf));
                hv.w = tanh_approx(fmaf(xn.w, wf, bf));
                *(float4*)&hs[fg * HSP + 4 * p4] = hv;
            }
        }

        ull acc[4][8];
        #pragma unroll
        for (int l = 0; l < 2; l++) {
            const float* bs = l ? bs1 : bs0;
            #pragma unroll
            for (int j = 0; j < 8; j++) {
                ull bb = pack2(bs[fb + 2*j], bs[fb + 2*j + 1]);
                acc[0][j] = bb; acc[1][j] = bb; acc[2][j] = bb; acc[3][j] = bb;
            }

            for (int c = 0; c < 4; c++) {
                int g = l * 4 + c;
                CP_WAIT(0);
                __syncthreads();                 // chunk g ready; prior reads done
                if (g + 1 < NCHNK) { ISSUE_CHUNK(g + 1); CP_COMMIT(); }

                const float* hrow = &hs[(c * CHUNK) * HSP + 4 * p4];
                const float* Wc   = Wb + (g & 1) * CHUNK * NEUR + fb;
                #pragma unroll 8
                for (int kl = 0; kl < CHUNK; kl++) {
                    float4 av = *(const float4*)(hrow + kl * HSP);
                    ull a0 = pack2(av.x, av.x);
                    ull a1 = pack2(av.y, av.y);
                    ull a2 = pack2(av.z, av.z);
                    ull a3 = pack2(av.w, av.w);
                    const ulonglong2* wr = (const ulonglong2*)(Wc + kl * NEUR);
                    ulonglong2 w0 = wr[0], w1 = wr[1], w2 = wr[2], w3 = wr[3];
                    ull b[8] = {w0.x, w0.y, w1.x, w1.y, w2.x, w2.y, w3.x, w3.y};
                    #pragma unroll
                    for (int j = 0; j < 8; j++) {
                        ffma2(acc[0][j], a0, b[j]);
                        ffma2(acc[1][j], a1, b[j]);
                        ffma2(acc[2][j], a2, b[j]);
                        ffma2(acc[3][j], a3, b[j]);
                    }
                }
            }
            __syncthreads();                     // all hs reads done

            if (l == 0) {
                #pragma unroll
                for (int j = 0; j < 8; j++) {
                    float2 v0 = unpack2(acc[0][j]);
                    float2 v1 = unpack2(acc[1][j]);
                    float2 v2 = unpack2(acc[2][j]);
                    float2 v3 = unpack2(acc[3][j]);
                    float4 ha, hb;
                    ha.x = tanh_approx(v0.x); ha.y = tanh_approx(v1.x);
                    ha.z = tanh_approx(v2.x); ha.w = tanh_approx(v3.x);
                    hb.x = tanh_approx(v0.y); hb.y = tanh_approx(v1.y);
                    hb.z = tanh_approx(v2.y); hb.w = tanh_approx(v3.y);
                    *(float4*)&hs[(fb + 2*j)     * HSP + 4 * p4] = ha;
                    *(float4*)&hs[(fb + 2*j + 1) * HSP + 4 * p4] = hb;
                }
            } else {
                float4 part = make_float4(0.f, 0.f, 0.f, 0.f);
                #pragma unroll
                for (int j = 0; j < 8; j++) {
                    float2 v0 = unpack2(acc[0][j]);
                    float2 v1 = unpack2(acc[1][j]);
                    float2 v2 = unpack2(acc[2][j]);
                    float2 v3 = unpack2(acc[3][j]);
                    float wa = wo[fb + 2*j], wb2 = wo[fb + 2*j + 1];
                    part.x = fmaf(tanh_approx(v0.x), wa, part.x);
                    part.x = fmaf(tanh_approx(v0.y), wb2, part.x);
                    part.y = fmaf(tanh_approx(v1.x), wa, part.y);
                    part.y = fmaf(tanh_approx(v1.y), wb2, part.y);
                    part.z = fmaf(tanh_approx(v2.x), wa, part.z);
                    part.z = fmaf(tanh_approx(v2.y), wb2, part.z);
                    part.w = fmaf(tanh_approx(v3.x), wa, part.w);
                    part.w = fmaf(tanh_approx(v3.y), wb2, part.w);
                }
                *(float4*)&opart[fbi * TILE + 4 * p4] = part;
            }
        }
        __syncthreads();

        if (tid < TILE) {
            int idx = sidx[tid];
            if (idx >= 0) {
                float acc_o = b_out[w];
                #pragma unroll
                for (int q = 0; q < 8; q++) acc_o += opart[q * TILE + tid];
                float xv  = xsr[tid];
                float xl  = (xv - mids[w])     * INV_SIGMA;
                float xr  = (xv - mids[w + 1]) * INV_SIGMA;
                float wnd = sigmoid_fast(-xl) * sigmoid_fast(xr);
                int h = min(NW - 1, max(0, (int)floorf(xv * (float)NW)));
                g_part[(w - h + HALO) * NPTS + idx] = wnd * acc_o;
            }
        }
        __syncthreads();   // opart/sidx reuse safe for next item
    }
}

extern "C" void kernel_launch(void* const* d_in, const int* in_sizes, int n_in,
                              void* d_out, int out_size) {
    const float* x     = (const float*)d_in[0];
    const float* means = (const float*)d_in[1];
    const float* stdv  = (const float*)d_in[2];
    const float* mids  = (const float*)d_in[3];
    const float* W_in  = (const float*)d_in[4];
    const float* b_in  = (const float*)d_in[5];
    const float* W_hid = (const float*)d_in[6];
    const float* b_hid = (const float*)d_in[7];
    const float* W_out = (const float*)d_in[8];
    const float* b_out = (const float*)d_in[9];

    const int smem_bytes = (NEUR * HSP + 2 * CHUNK * NEUR
                          + 3 * TILE + 5 * NEUR + 8 * TILE + NW + 2) * sizeof(float);
    cudaFuncSetAttribute(fbpinn_kernel, cudaFuncAttributeMaxDynamicSharedMemorySize,
                         smem_bytes);

    build_lists<<<NPTS / 256, 256>>>(x);
    fbpinn_kernel<<<NCTA, THREADS, smem_bytes>>>(x, means, stdv, mids, W_in, b_in,
                                                 W_hid, b_hid, W_out, b_out);
    fbpinn_reduce<<<NPTS / 256, 256>>>(x, (float*)d_out);
}

// round 15
// speedup vs baseline: 1.0003x; 1.0003x over previous
#include <cuda_runtime.h>
#include <cstdint>

#define NW 16
#define NEUR 128
#define NPTS 65536
#define TILE 128
#define THREADS 256
#define INV_SIGMA 50.0f
#define HALO 3
#define NSLOT (2*HALO+1)
#define HSP 132              // hs row pitch (floats); 16B-aligned rows
#define CHUNK 32
#define NCHNK 8
#define NCTA 296             // 2 per SM x 148 SMs, persistent

typedef unsigned long long ull;

__device__ int   g_cnt[NW];          // statically zero; reduce re-zeros each run
__device__ int   g_work;
__device__ int   g_list[NW * NPTS];
__device__ float g_part[NSLOT * NPTS];

static __device__ __forceinline__ float tanh_approx(float x) {
    float r; asm("tanh.approx.f32 %0, %1;" : "=f"(r) : "f"(x)); return r;
}
static __device__ __forceinline__ float sigmoid_fast(float x) {
    return 1.0f / (1.0f + __expf(-x));
}
static __device__ __forceinline__ void ffma2(ull& d, ull a, ull b) {
    asm("fma.rn.f32x2 %0, %1, %2, %0;" : "+l"(d) : "l"(a), "l"(b));
}
static __device__ __forceinline__ ull pack2(float lo, float hi) {
    ull r; asm("mov.b64 %0, {%1, %2};" : "=l"(r) : "f"(lo), "f"(hi)); return r;
}
static __device__ __forceinline__ float2 unpack2(ull v) {
    float2 r; asm("mov.b64 {%0, %1}, %2;" : "=f"(r.x), "=f"(r.y) : "l"(v)); return r;
}
static __device__ __forceinline__ uint32_t smem_u32(const void* p) {
    uint32_t a;
    asm("{ .reg .u64 t; cvta.to.shared.u64 t, %1; cvt.u32.u64 %0, t; }" : "=r"(a) : "l"(p));
    return a;
}
static __device__ __forceinline__ void cp16(uint32_t dst, const void* src) {
    asm volatile("cp.async.ca.shared.global [%0], [%1], 16;" :: "r"(dst), "l"(src));
}
#define CP_COMMIT() asm volatile("cp.async.commit_group;" ::: "memory")
#define CP_WAIT(n)  asm volatile("cp.async.wait_group %0;" :: "n"(n) : "memory")

// ---------------- small kernels ----------------
// Two-level counter aggregation: smem ranks per CTA, ONE global atomic per
// (CTA, window) -> 256 atomics/address instead of ~900 serialized leaders.
__global__ void build_lists(const float* __restrict__ x) {
    __shared__ int scount[NW];
    __shared__ int sbase[NW];
    const int tid = threadIdx.x;
    const int p   = blockIdx.x * blockDim.x + tid;

    if (tid < NW) scount[tid] = 0;
    __syncthreads();

    float xv = x[p];
    int h = min(NW - 1, max(0, (int)floorf(xv * (float)NW)));

    int rank[NSLOT];
    #pragma unroll
    for (int dw = -HALO; dw <= HALO; dw++) {
        int w = h + dw;
        rank[dw + HALO] = (w >= 0 && w < NW) ? atomicAdd(&scount[w], 1) : -1;
    }
    __syncthreads();

    if (tid < NW) sbase[tid] = (scount[tid] > 0)
                             ? atomicAdd(&g_cnt[tid], scount[tid]) : 0;
    __syncthreads();

    #pragma unroll
    for (int dw = -HALO; dw <= HALO; dw++) {
        int w = h + dw;
        if (rank[dw + HALO] >= 0)
            g_list[w * NPTS + sbase[w] + rank[dw + HALO]] = p;
    }
}

__global__ void fbpinn_reduce(const float* __restrict__ x, float* __restrict__ out) {
    int n = blockIdx.x * blockDim.x + threadIdx.x;
    if (n < NPTS) {
        int h = min(NW - 1, max(0, (int)floorf(x[n] * (float)NW)));
        float s = 0.0f;
        #pragma unroll
        for (int dw = -HALO; dw <= HALO; dw++) {
            int w = h + dw;
            if (w >= 0 && w < NW) s += g_part[(dw + HALO) * NPTS + n];
        }
        out[n] = s;
        // reset counters for the next graph replay
        if (n < NW) g_cnt[n] = 0;
        if (n == NW) g_work = 0;
    }
}

// ---------------- main kernel: persistent, 2 CTAs/SM (unchanged) ----------------
__global__ __launch_bounds__(THREADS, 2) void fbpinn_kernel(
    const float* __restrict__ x,    const float* __restrict__ means,
    const float* __restrict__ stdv, const float* __restrict__ mids,
    const float* __restrict__ W_in, const float* __restrict__ b_in,
    const float* __restrict__ W_hid,const float* __restrict__ b_hid,
    const float* __restrict__ W_out,const float* __restrict__ b_out)
{
    extern __shared__ float smem[];
    float* hs    = smem;                       // [128][132]  67584 B
    float* Wb    = hs + NEUR * HSP;            // [2][32][128] 32768 B ping-pong
    float* xsn   = Wb + 2 * CHUNK * NEUR;      // [128]
    float* xsr   = xsn + TILE;
    int*   sidx  = (int*)(xsr + TILE);
    float* win   = (float*)(sidx + TILE);
    float* bin   = win + NEUR;
    float* wo    = bin + NEUR;
    float* bs0   = wo + NEUR;
    float* bs1   = bs0 + NEUR;
    float* opart = bs1 + NEUR;                 // [8][128]
    int*   pref  = (int*)(opart + 8 * TILE);   // [NW+1]
    int*   itm   = pref + NW + 1;              // [1]

    const int tid = threadIdx.x;
    const int p4  = tid & 31;                  // point quad: 4*p4 .. 4*p4+3
    const int fbi = tid >> 5;                  // feature block 0..7
    const int fb  = fbi * 16;

    if (tid == 0) {
        int s = 0;
        pref[0] = 0;
        #pragma unroll
        for (int i = 0; i < NW; i++) {
            s += (g_cnt[i] + TILE - 1) / TILE;
            pref[i + 1] = s;
        }
    }
    __syncthreads();
    const int total = pref[NW];
    const size_t lstep = (size_t)NW * NEUR * NEUR;

    for (;;) {
        if (tid == 0) itm[0] = atomicAdd(&g_work, 1);
        __syncthreads();
        const int item = itm[0];
        if (item >= total) break;

        int w = 0;
        #pragma unroll
        for (int i = 1; i < NW; i++) if (item >= pref[i]) w = i;
        const int p0  = (item - pref[w]) * TILE;
        const int cnt = g_cnt[w];
        const size_t wbase = (size_t)w * NEUR * NEUR;

        #define ISSUE_CHUNK(g) do {                                              \
            const char* _src = (const char*)(W_hid + ((g) >> 2) * lstep + wbase  \
                                             + ((g) & 3) * CHUNK * NEUR);        \
            uint32_t _dst = smem_u32(Wb + ((g) & 1) * CHUNK * NEUR);             \
            _Pragma("unroll")                                                    \
            for (int _i = 0; _i < 4; _i++)                                       \
                cp16(_dst + (tid + _i * THREADS) * 16,                           \
                     _src + (tid + _i * THREADS) * 16);                          \
        } while (0)

        ISSUE_CHUNK(0);
        CP_COMMIT();

        if (tid < TILE) {
            int i = p0 + tid;
            int idx = g_list[w * NPTS + ((i < cnt) ? i : p0)];
            sidx[tid] = (i < cnt) ? idx : -1;
            float xv = x[idx];
            xsr[tid] = xv;
            xsn[tid] = (xv - means[w]) / stdv[w];
        }
        if (tid < NEUR) {
            win[tid] = W_in[w * NEUR + tid];
            bin[tid] = b_in[w * NEUR + tid];
            wo[tid]  = W_out[w * NEUR + tid];
            bs0[tid] = b_hid[(size_t)w * NEUR + tid];
            bs1[tid] = b_hid[(size_t)(NW + w) * NEUR + tid];
        }
        __syncthreads();

        // ---- layer 0: 4 points x 16 features per thread ----
        {
            float4 xn = *(const float4*)&xsn[4 * p4];
            #pragma unroll
            for (int f = 0; f < 16; f++) {
                int fg = fb + f;
                float wf = win[fg], bf = bin[fg];
                float4 hv;
                hv.x = tanh_approx(fmaf(xn.x, wf, bf));
                hv.y = tanh_approx(fmaf(xn.y, wf, bf));
                hv.z = tanh_approx(fmaf(xn.z, wf, bf));
                hv.w = tanh_approx(fmaf(xn.w, wf, bf));
                *(float4*)&hs[fg * HSP + 4 * p4] = hv;
            }
        }

        ull acc[4][8];
        #pragma unroll
        for (int l = 0; l < 2; l++) {
            const float* bs = l ? bs1 : bs0;
            #pragma unroll
            for (int j = 0; j < 8; j++) {
                ull bb = pack2(bs[fb + 2*j], bs[fb + 2*j + 1]);
                acc[0][j] = bb; acc[1][j] = bb; acc[2][j] = bb; acc[3][j] = bb;
            }

            for (int c = 0; c < 4; c++) {
                int g = l * 4 + c;
                CP_WAIT(0);
                __syncthreads();                 // chunk g ready; prior reads done
                if (g + 1 < NCHNK) { ISSUE_CHUNK(g + 1); CP_COMMIT(); }

                const float* hrow = &hs[(c * CHUNK) * HSP + 4 * p4];
                const float* Wc   = Wb + (g & 1) * CHUNK * NEUR + fb;
                #pragma unroll 8
                for (int kl = 0; kl < CHUNK; kl++) {
                    float4 av = *(const float4*)(hrow + kl * HSP);
                    ull a0 = pack2(av.x, av.x);
                    ull a1 = pack2(av.y, av.y);
                    ull a2 = pack2(av.z, av.z);
                    ull a3 = pack2(av.w, av.w);
                    const ulonglong2* wr = (const ulonglong2*)(Wc + kl * NEUR);
                    ulonglong2 w0 = wr[0], w1 = wr[1], w2 = wr[2], w3 = wr[3];
                    ull b[8] = {w0.x, w0.y, w1.x, w1.y, w2.x, w2.y, w3.x, w3.y};
                    #pragma unroll
                    for (int j = 0; j < 8; j++) {
                        ffma2(acc[0][j], a0, b[j]);
                        ffma2(acc[1][j], a1, b[j]);
                        ffma2(acc[2][j], a2, b[j]);
                        ffma2(acc[3][j], a3, b[j]);
                    }
                }
            }
            __syncthreads();                     // all hs reads done

            if (l == 0) {
                #pragma unroll
                for (int j = 0; j < 8; j++) {
                    float2 v0 = unpack2(acc[0][j]);
                    float2 v1 = unpack2(acc[1][j]);
                    float2 v2 = unpack2(acc[2][j]);
                    float2 v3 = unpack2(acc[3][j]);
                    float4 ha, hb;
                    ha.x = tanh_approx(v0.x); ha.y = tanh_approx(v1.x);
                    ha.z = tanh_approx(v2.x); ha.w = tanh_approx(v3.x);
                    hb.x = tanh_approx(v0.y); hb.y = tanh_approx(v1.y);
                    hb.z = tanh_approx(v2.y); hb.w = tanh_approx(v3.y);
                    *(float4*)&hs[(fb + 2*j)     * HSP + 4 * p4] = ha;
                    *(float4*)&hs[(fb + 2*j + 1) * HSP + 4 * p4] = hb;
                }
            } else {
                float4 part = make_float4(0.f, 0.f, 0.f, 0.f);
                #pragma unroll
                for (int j = 0; j < 8; j++) {
                    float2 v0 = unpack2(acc[0][j]);
                    float2 v1 = unpack2(acc[1][j]);
                    float2 v2 = unpack2(acc[2][j]);
                    float2 v3 = unpack2(acc[3][j]);
                    float wa = wo[fb + 2*j], wb2 = wo[fb + 2*j + 1];
                    part.x = fmaf(tanh_approx(v0.x), wa, part.x);
                    part.x = fmaf(tanh_approx(v0.y), wb2, part.x);
                    part.y = fmaf(tanh_approx(v1.x), wa, part.y);
                    part.y = fmaf(tanh_approx(v1.y), wb2, part.y);
                    part.z = fmaf(tanh_approx(v2.x), wa, part.z);
                    part.z = fmaf(tanh_approx(v2.y), wb2, part.z);
                    part.w = fmaf(tanh_approx(v3.x), wa, part.w);
                    part.w = fmaf(tanh_approx(v3.y), wb2, part.w);
                }
                *(float4*)&opart[fbi * TILE + 4 * p4] = part;
            }
        }
        __syncthreads();

        if (tid < TILE) {
            int idx = sidx[tid];
            if (idx >= 0) {
                float acc_o = b_out[w];
                #pragma unroll
                for (int q = 0; q < 8; q++) acc_o += opart[q * TILE + tid];
                float xv  = xsr[tid];
                float xl  = (xv - mids[w])     * INV_SIGMA;
                float xr  = (xv - mids[w + 1]) * INV_SIGMA;
                float wnd = sigmoid_fast(-xl) * sigmoid_fast(xr);
                int h = min(NW - 1, max(0, (int)floorf(xv * (float)NW)));
                g_part[(w - h + HALO) * NPTS + idx] = wnd * acc_o;
            }
        }
        __syncthreads();   // opart/sidx reuse safe for next item
    }
}

extern "C" void kernel_launch(void* const* d_in, const int* in_sizes, int n_in,
                              void* d_out, int out_size) {
    const float* x     = (const float*)d_in[0];
    const float* means = (const float*)d_in[1];
    const float* stdv  = (const float*)d_in[2];
    const float* mids  = (const float*)d_in[3];
    const float* W_in  = (const float*)d_in[4];
    const float* b_in  = (const float*)d_in[5];
    const float* W_hid = (const float*)d_in[6];
    const float* b_hid = (const float*)d_in[7];
    const float* W_out = (const float*)d_in[8];
    const float* b_out = (const float*)d_in[9];

    const int smem_bytes = (NEUR * HSP + 2 * CHUNK * NEUR
                          + 3 * TILE + 5 * NEUR + 8 * TILE + NW + 2) * sizeof(float);
    cudaFuncSetAttribute(fbpinn_kernel, cudaFuncAttributeMaxDynamicSharedMemorySize,
                         smem_bytes);

    build_lists<<<NPTS / 256, 256>>>(x);
    fbpinn_kernel<<<NCTA, THREADS, smem_bytes>>>(x, means, stdv, mids, W_in, b_in,
                                                 W_hid, b_hid, W_out, b_out);
    fbpinn_reduce<<<NPTS / 256, 256>>>(x, (float*)d_out);
}

// round 16
// speedup vs baseline: 1.0011x; 1.0007x over previous
#include <cuda_runtime.h>
#include <cstdint>

#define NW 16
#define NEUR 128
#define NPTS 65536
#define TILE 128
#define THREADS 256
#define INV_SIGMA 50.0f
#define HALO 3
#define NSLOT (2*HALO+1)
#define HSP 132              // hs row pitch (floats); 16B-aligned rows
#define CHUNK 32
#define NCHNK 8
#define NCTA 296             // 2 per SM x 148 SMs, persistent

typedef unsigned long long ull;

__device__ int   g_cnt[NW];          // statically zero; reduce re-zeros each run
__device__ int   g_work;
__device__ int   g_list[NW * NPTS];
__device__ float g_part[NSLOT * NPTS];

static __device__ __forceinline__ float tanh_approx(float x) {
    float r; asm("tanh.approx.f32 %0, %1;" : "=f"(r) : "f"(x)); return r;
}
static __device__ __forceinline__ float sigmoid_fast(float x) {
    return 1.0f / (1.0f + __expf(-x));
}
static __device__ __forceinline__ void ffma2(ull& d, ull a, ull b) {
    asm("fma.rn.f32x2 %0, %1, %2, %0;" : "+l"(d) : "l"(a), "l"(b));
}
static __device__ __forceinline__ ull pack2(float lo, float hi) {
    ull r; asm("mov.b64 %0, {%1, %2};" : "=l"(r) : "f"(lo), "f"(hi)); return r;
}
static __device__ __forceinline__ float2 unpack2(ull v) {
    float2 r; asm("mov.b64 {%0, %1}, %2;" : "=f"(r.x), "=f"(r.y) : "l"(v)); return r;
}
static __device__ __forceinline__ uint32_t smem_u32(const void* p) {
    uint32_t a;
    asm("{ .reg .u64 t; cvta.to.shared.u64 t, %1; cvt.u32.u64 %0, t; }" : "=r"(a) : "l"(p));
    return a;
}
static __device__ __forceinline__ void cp16(uint32_t dst, const void* src) {
    asm volatile("cp.async.ca.shared.global [%0], [%1], 16;" :: "r"(dst), "l"(src));
}
#define CP_COMMIT() asm volatile("cp.async.commit_group;" ::: "memory")
#define CP_WAIT(n)  asm volatile("cp.async.wait_group %0;" :: "n"(n) : "memory")

// ---------------- small kernels ----------------
// Two-level counter aggregation: smem ranks per CTA, ONE global atomic per
// (CTA, window) -> 256 atomics/address instead of ~900 serialized leaders.
__global__ void build_lists(const float* __restrict__ x) {
    __shared__ int scount[NW];
    __shared__ int sbase[NW];
    const int tid = threadIdx.x;
    const int p   = blockIdx.x * blockDim.x + tid;

    if (tid < NW) scount[tid] = 0;
    __syncthreads();

    float xv = x[p];
    int h = min(NW - 1, max(0, (int)floorf(xv * (float)NW)));

    int rank[NSLOT];
    #pragma unroll
    for (int dw = -HALO; dw <= HALO; dw++) {
        int w = h + dw;
        rank[dw + HALO] = (w >= 0 && w < NW) ? atomicAdd(&scount[w], 1) : -1;
    }
    __syncthreads();

    if (tid < NW) sbase[tid] = (scount[tid] > 0)
                             ? atomicAdd(&g_cnt[tid], scount[tid]) : 0;
    __syncthreads();

    #pragma unroll
    for (int dw = -HALO; dw <= HALO; dw++) {
        int w = h + dw;
        if (rank[dw + HALO] >= 0)
            g_list[w * NPTS + sbase[w] + rank[dw + HALO]] = p;
    }
}

__global__ void fbpinn_reduce(const float* __restrict__ x, float* __restrict__ out) {
    int n = blockIdx.x * blockDim.x + threadIdx.x;
    if (n < NPTS) {
        int h = min(NW - 1, max(0, (int)floorf(x[n] * (float)NW)));
        float s = 0.0f;
        #pragma unroll
        for (int dw = -HALO; dw <= HALO; dw++) {
            int w = h + dw;
            if (w >= 0 && w < NW) s += g_part[(dw + HALO) * NPTS + n];
        }
        out[n] = s;
        // reset counters for the next graph replay
        if (n < NW) g_cnt[n] = 0;
        if (n == NW) g_work = 0;
    }
}

// ---------------- main kernel: persistent, 2 CTAs/SM (unchanged) ----------------
__global__ __launch_bounds__(THREADS, 2) void fbpinn_kernel(
    const float* __restrict__ x,    const float* __restrict__ means,
    const float* __restrict__ stdv, const float* __restrict__ mids,
    const float* __restrict__ W_in, const float* __restrict__ b_in,
    const float* __restrict__ W_hid,const float* __restrict__ b_hid,
    const float* __restrict__ W_out,const float* __restrict__ b_out)
{
    extern __shared__ float smem[];
    float* hs    = smem;                       // [128][132]  67584 B
    float* Wb    = hs + NEUR * HSP;            // [2][32][128] 32768 B ping-pong
    float* xsn   = Wb + 2 * CHUNK * NEUR;      // [128]
    float* xsr   = xsn + TILE;
    int*   sidx  = (int*)(xsr + TILE);
    float* win   = (float*)(sidx + TILE);
    float* bin   = win + NEUR;
    float* wo    = bin + NEUR;
    float* bs0   = wo + NEUR;
    float* bs1   = bs0 + NEUR;
    float* opart = bs1 + NEUR;                 // [8][128]
    int*   pref  = (int*)(opart + 8 * TILE);   // [NW+1]
    int*   itm   = pref + NW + 1;              // [1]

    const int tid = threadIdx.x;
    const int p4  = tid & 31;                  // point quad: 4*p4 .. 4*p4+3
    const int fbi = tid >> 5;                  // feature block 0..7
    const int fb  = fbi * 16;

    if (tid == 0) {
        int s = 0;
        pref[0] = 0;
        #pragma unroll
        for (int i = 0; i < NW; i++) {
            s += (g_cnt[i] + TILE - 1) / TILE;
            pref[i + 1] = s;
        }
    }
    __syncthreads();
    const int total = pref[NW];
    const size_t lstep = (size_t)NW * NEUR * NEUR;

    for (;;) {
        if (tid == 0) itm[0] = atomicAdd(&g_work, 1);
        __syncthreads();
        const int item = itm[0];
        if (item >= total) break;

        int w = 0;
        #pragma unroll
        for (int i = 1; i < NW; i++) if (item >= pref[i]) w = i;
        const int p0  = (item - pref[w]) * TILE;
        const int cnt = g_cnt[w];
        const size_t wbase = (size_t)w * NEUR * NEUR;

        #define ISSUE_CHUNK(g) do {                                              \
            const char* _src = (const char*)(W_hid + ((g) >> 2) * lstep + wbase  \
                                             + ((g) & 3) * CHUNK * NEUR);        \
            uint32_t _dst = smem_u32(Wb + ((g) & 1) * CHUNK * NEUR);             \
            _Pragma("unroll")                                                    \
            for (int _i = 0; _i < 4; _i++)                                       \
                cp16(_dst + (tid + _i * THREADS) * 16,                           \
                     _src + (tid + _i * THREADS) * 16);                          \
        } while (0)

        ISSUE_CHUNK(0);
        CP_COMMIT();

        if (tid < TILE) {
            int i = p0 + tid;
            int idx = g_list[w * NPTS + ((i < cnt) ? i : p0)];
            sidx[tid] = (i < cnt) ? idx : -1;
            float xv = x[idx];
            xsr[tid] = xv;
            xsn[tid] = (xv - means[w]) / stdv[w];
        }
        if (tid < NEUR) {
            win[tid] = W_in[w * NEUR + tid];
            bin[tid] = b_in[w * NEUR + tid];
            wo[tid]  = W_out[w * NEUR + tid];
            bs0[tid] = b_hid[(size_t)w * NEUR + tid];
            bs1[tid] = b_hid[(size_t)(NW + w) * NEUR + tid];
        }
        __syncthreads();

        // ---- layer 0: 4 points x 16 features per thread ----
        {
            float4 xn = *(const float4*)&xsn[4 * p4];
            #pragma unroll
            for (int f = 0; f < 16; f++) {
                int fg = fb + f;
                float wf = win[fg], bf = bin[fg];
                float4 hv;
                hv.x = tanh_approx(fmaf(xn.x, wf, bf));
                hv.y = tanh_approx(fmaf(xn.y, wf, bf));
                hv.z = tanh_approx(fmaf(xn.z, wf, bf));
                hv.w = tanh_approx(fmaf(xn.w, wf, bf));
                *(float4*)&hs[fg * HSP + 4 * p4] = hv;
            }
        }

        ull acc[4][8];
        #pragma unroll
        for (int l = 0; l < 2; l++) {
            const float* bs = l ? bs1 : bs0;
            #pragma unroll
            for (int j = 0; j < 8; j++) {
                ull bb = pack2(bs[fb + 2*j], bs[fb + 2*j + 1]);
                acc[0][j] = bb; acc[1][j] = bb; acc[2][j] = bb; acc[3][j] = bb;
            }

            for (int c = 0; c < 4; c++) {
                int g = l * 4 + c;
                CP_WAIT(0);
                __syncthreads();                 // chunk g ready; prior reads done
                if (g + 1 < NCHNK) { ISSUE_CHUNK(g + 1); CP_COMMIT(); }

                const float* hrow = &hs[(c * CHUNK) * HSP + 4 * p4];
                const float* Wc   = Wb + (g & 1) * CHUNK * NEUR + fb;
                #pragma unroll 8
                for (int kl = 0; kl < CHUNK; kl++) {
                    float4 av = *(const float4*)(hrow + kl * HSP);
                    ull a0 = pack2(av.x, av.x);
                    ull a1 = pack2(av.y, av.y);
                    ull a2 = pack2(av.z, av.z);
                    ull a3 = pack2(av.w, av.w);
                    const ulonglong2* wr = (const ulonglong2*)(Wc + kl * NEUR);
                    ulonglong2 w0 = wr[0], w1 = wr[1], w2 = wr[2], w3 = wr[3];
                    ull b[8] = {w0.x, w0.y, w1.x, w1.y, w2.x, w2.y, w3.x, w3.y};
                    #pragma unroll
                    for (int j = 0; j < 8; j++) {
                        ffma2(acc[0][j], a0, b[j]);
                        ffma2(acc[1][j], a1, b[j]);
                        ffma2(acc[2][j], a2, b[j]);
                        ffma2(acc[3][j], a3, b[j]);
                    }
                }
            }
            __syncthreads();                     // all hs reads done

            if (l == 0) {
                #pragma unroll
                for (int j = 0; j < 8; j++) {
                    float2 v0 = unpack2(acc[0][j]);
                    float2 v1 = unpack2(acc[1][j]);
                    float2 v2 = unpack2(acc[2][j]);
                    float2 v3 = unpack2(acc[3][j]);
                    float4 ha, hb;
                    ha.x = tanh_approx(v0.x); ha.y = tanh_approx(v1.x);
                    ha.z = tanh_approx(v2.x); ha.w = tanh_approx(v3.x);
                    hb.x = tanh_approx(v0.y); hb.y = tanh_approx(v1.y);
                    hb.z = tanh_approx(v2.y); hb.w = tanh_approx(v3.y);
                    *(float4*)&hs[(fb + 2*j)     * HSP + 4 * p4] = ha;
                    *(float4*)&hs[(fb + 2*j + 1) * HSP + 4 * p4] = hb;
                }
            } else {
                float4 part = make_float4(0.f, 0.f, 0.f, 0.f);
                #pragma unroll
                for (int j = 0; j < 8; j++) {
                    float2 v0 = unpack2(acc[0][j]);
                    float2 v1 = unpack2(acc[1][j]);
                    float2 v2 = unpack2(acc[2][j]);
                    float2 v3 = unpack2(acc[3][j]);
                    float wa = wo[fb + 2*j], wb2 = wo[fb + 2*j + 1];
                    part.x = fmaf(tanh_approx(v0.x), wa, part.x);
                    part.x = fmaf(tanh_approx(v0.y), wb2, part.x);
                    part.y = fmaf(tanh_approx(v1.x), wa, part.y);
                    part.y = fmaf(tanh_approx(v1.y), wb2, part.y);
                    part.z = fmaf(tanh_approx(v2.x), wa, part.z);
                    part.z = fmaf(tanh_approx(v2.y), wb2, part.z);
                    part.w = fmaf(tanh_approx(v3.x), wa, part.w);
                    part.w = fmaf(tanh_approx(v3.y), wb2, part.w);
                }
                *(float4*)&opart[fbi * TILE + 4 * p4] = part;
            }
        }
        __syncthreads();

        if (tid < TILE) {
            int idx = sidx[tid];
            if (idx >= 0) {
                float acc_o = b_out[w];
                #pragma unroll
                for (int q = 0; q < 8; q++) acc_o += opart[q * TILE + tid];
                float xv  = xsr[tid];
                float xl  = (xv - mids[w])     * INV_SIGMA;
                float xr  = (xv - mids[w + 1]) * INV_SIGMA;
                float wnd = sigmoid_fast(-xl) * sigmoid_fast(xr);
                int h = min(NW - 1, max(0, (int)floorf(xv * (float)NW)));
                g_part[(w - h + HALO) * NPTS + idx] = wnd * acc_o;
            }
        }
        __syncthreads();   // opart/sidx reuse safe for next item
    }
}

extern "C" void kernel_launch(void* const* d_in, const int* in_sizes, int n_in,
                              void* d_out, int out_size) {
    const float* x     = (const float*)d_in[0];
    const float* means = (const float*)d_in[1];
    const float* stdv  = (const float*)d_in[2];
    const float* mids  = (const float*)d_in[3];
    const float* W_in  = (const float*)d_in[4];
    const float* b_in  = (const float*)d_in[5];
    const float* W_hid = (const float*)d_in[6];
    const float* b_hid = (const float*)d_in[7];
    const float* W_out = (const float*)d_in[8];
    const float* b_out = (const float*)d_in[9];

    const int smem_bytes = (NEUR * HSP + 2 * CHUNK * NEUR
                          + 3 * TILE + 5 * NEUR + 8 * TILE + NW + 2) * sizeof(float);
    cudaFuncSetAttribute(fbpinn_kernel, cudaFuncAttributeMaxDynamicSharedMemorySize,
                         smem_bytes);

    build_lists<<<NPTS / 256, 256>>>(x);
    fbpinn_kernel<<<NCTA, THREADS, smem_bytes>>>(x, means, stdv, mids, W_in, b_in,
                                                 W_hid, b_hid, W_out, b_out);
    fbpinn_reduce<<<NPTS / 256, 256>>>(x, (float*)d_out);
}